// round 1
// baseline (speedup 1.0000x reference)
#include <cuda_runtime.h>
#include <math.h>

// Problem constants
#define BATCH   8192
#define DIM     256
#define NCOEF   5
#define KDIM    (DIM * NCOEF)   // 1280
#define NLAYERS 2
#define LN_EPS  1e-6f

// Scratch (static device globals — allocation-free per harness rules)
__device__ float g_dm[BATCH * KDIM];           // design matrix [B][K], K = i*5 + c
__device__ float g_h [BATCH * DIM];            // intermediate activations
__device__ float g_Bt[NLAYERS * KDIM * DIM];   // transposed coefs [l][k][o]

// ---------------------------------------------------------------------------
// Kernel 0: transpose coefs [l][i][o][c] -> Bt[l][k=i*5+c][o]
// ---------------------------------------------------------------------------
__global__ void transpose_coefs(const float* __restrict__ coefs,
                                float* __restrict__ Bt) {
    int idx = blockIdx.x * blockDim.x + threadIdx.x;
    const int total = NLAYERS * KDIM * DIM;
    if (idx >= total) return;
    int o = idx & (DIM - 1);
    int k = (idx >> 8) % KDIM;
    int l = idx / (KDIM * DIM);
    int i = k / NCOEF;
    int c = k - i * NCOEF;
    Bt[idx] = coefs[((l * DIM + i) * DIM + o) * NCOEF + c];
}

// ---------------------------------------------------------------------------
// Kernel 1: LayerNorm + tanh + Jacobi design matrix.
// One block (256 threads) per batch row. dm[b][i*5+c] written.
// ---------------------------------------------------------------------------
__global__ void __launch_bounds__(DIM)
ln_jacobi(const float* __restrict__ h,
          const float* __restrict__ scale,
          const float* __restrict__ bias,
          const float* __restrict__ alphas,
          int layer,
          float* __restrict__ dm) {
    const int b = blockIdx.x;
    const int i = threadIdx.x;

    float v = h[b * DIM + i];

    __shared__ float red[8];

    // mean
    float s = v;
    #pragma unroll
    for (int off = 16; off; off >>= 1) s += __shfl_xor_sync(0xFFFFFFFFu, s, off);
    if ((i & 31) == 0) red[i >> 5] = s;
    __syncthreads();
    float mu = (red[0] + red[1] + red[2] + red[3] +
                red[4] + red[5] + red[6] + red[7]) * (1.0f / DIM);
    __syncthreads();

    // variance
    float d = v - mu;
    float s2 = d * d;
    #pragma unroll
    for (int off = 16; off; off >>= 1) s2 += __shfl_xor_sync(0xFFFFFFFFu, s2, off);
    if ((i & 31) == 0) red[i >> 5] = s2;
    __syncthreads();
    float var = (red[0] + red[1] + red[2] + red[3] +
                 red[4] + red[5] + red[6] + red[7]) * (1.0f / DIM);

    float hn = d * rsqrtf(var + LN_EPS) * scale[i] + bias[i];
    float x  = tanhf(hn);
    float a  = tanhf(alphas[layer]);

    // Jacobi recurrence P_0..P_4^{(a,a)}(x)
    float P[NCOEF];
    P[0] = 1.0f;
    P[1] = (a + 1.0f) * x;
    #pragma unroll
    for (int k = 2; k < NCOEF; k++) {
        float kf = (float)k;
        float t  = 2.0f * kf + 2.0f * a;
        float A  = 2.0f * kf * (kf + 2.0f * a) * (t - 2.0f);
        float B  = (t - 1.0f) * t * (t - 2.0f);
        float C  = 2.0f * (kf + a - 1.0f) * (kf + a - 1.0f) * t;
        P[k] = (B * x * P[k - 1] - C * P[k - 2]) / A;
    }

    float* o = dm + (size_t)b * KDIM + i * NCOEF;
    #pragma unroll
    for (int c = 0; c < NCOEF; c++) o[c] = P[c];
}

// ---------------------------------------------------------------------------
// Kernel 2: fp32 tiled GEMM. C[M,N] = (1/DIM) * A[M,K] @ B[K,N]
// M=8192, N=256, K=1280. BM=64, BN=64, BK=16, TM=TN=4, 256 threads.
// ---------------------------------------------------------------------------
__global__ void __launch_bounds__(256)
gemm_kernel(const float* __restrict__ A,
            const float* __restrict__ B,
            float* __restrict__ C) {
    constexpr int BM = 64, BN = 64, BK = 16;
    constexpr int N = DIM, K = KDIM;

    __shared__ float As[BK][BM];
    __shared__ float Bs[BK][BN];

    const int bm = blockIdx.x * BM;
    const int bn = blockIdx.y * BN;
    const int tid = threadIdx.x;

    // A load: 64x16 tile = 256 float4. thread -> (row = tid/4, 4 cols = (tid%4)*4)
    const int arow = tid >> 2;
    const int acol = (tid & 3) * 4;
    // B load: 16x64 tile = 256 float4. thread -> (row = tid/16, 4 cols = (tid%16)*4)
    const int brow = tid >> 4;
    const int bcol = (tid & 15) * 4;

    const int tm = (tid >> 4) * 4;   // 0..60
    const int tn = (tid & 15) * 4;   // 0..60

    float acc[4][4];
    #pragma unroll
    for (int m = 0; m < 4; m++)
        #pragma unroll
        for (int n = 0; n < 4; n++) acc[m][n] = 0.0f;

    for (int k0 = 0; k0 < K; k0 += BK) {
        float4 av = *(const float4*)(A + (size_t)(bm + arow) * K + k0 + acol);
        As[acol + 0][arow] = av.x;
        As[acol + 1][arow] = av.y;
        As[acol + 2][arow] = av.z;
        As[acol + 3][arow] = av.w;

        float4 bv = *(const float4*)(B + (size_t)(k0 + brow) * N + bn + bcol);
        *(float4*)&Bs[brow][bcol] = bv;

        __syncthreads();

        #pragma unroll
        for (int k = 0; k < BK; k++) {
            float ar[4], br[4];
            #pragma unroll
            for (int j = 0; j < 4; j++) ar[j] = As[k][tm + j];
            #pragma unroll
            for (int j = 0; j < 4; j++) br[j] = Bs[k][tn + j];
            #pragma unroll
            for (int m = 0; m < 4; m++)
                #pragma unroll
                for (int n = 0; n < 4; n++)
                    acc[m][n] = fmaf(ar[m], br[n], acc[m][n]);
        }
        __syncthreads();
    }

    constexpr float inv = 1.0f / (float)DIM;
    #pragma unroll
    for (int m = 0; m < 4; m++) {
        #pragma unroll
        for (int n = 0; n < 4; n++) {
            C[(size_t)(bm + tm + m) * N + bn + tn + n] = acc[m][n] * inv;
        }
    }
}

// ---------------------------------------------------------------------------
// Launch
// ---------------------------------------------------------------------------
extern "C" void kernel_launch(void* const* d_in, const int* in_sizes, int n_in,
                              void* d_out, int out_size) {
    const float* x        = (const float*)d_in[0];  // [8192, 256]
    const float* coefs    = (const float*)d_in[1];  // [2, 256, 256, 5]
    const float* alphas   = (const float*)d_in[2];  // [2]
    const float* ln_scale = (const float*)d_in[3];  // [2, 256]
    const float* ln_bias  = (const float*)d_in[4];  // [2, 256]
    float* out = (float*)d_out;                     // [8192, 256]

    float* dm; cudaGetSymbolAddress((void**)&dm, g_dm);
    float* hbuf; cudaGetSymbolAddress((void**)&hbuf, g_h);
    float* Bt; cudaGetSymbolAddress((void**)&Bt, g_Bt);

    // 0: transpose coefs for both layers
    {
        int total = NLAYERS * KDIM * DIM;
        transpose_coefs<<<(total + 255) / 256, 256>>>(coefs, Bt);
    }

    dim3 ggrid(BATCH / 64, DIM / 64);

    // Layer 0
    ln_jacobi<<<BATCH, DIM>>>(x, ln_scale, ln_bias, alphas, 0, dm);
    gemm_kernel<<<ggrid, 256>>>(dm, Bt, hbuf);

    // Layer 1
    ln_jacobi<<<BATCH, DIM>>>(hbuf, ln_scale + DIM, ln_bias + DIM, alphas, 1, dm);
    gemm_kernel<<<ggrid, 256>>>(dm, Bt + (size_t)KDIM * DIM, out);
}

// round 3
// speedup vs baseline: 3.0153x; 3.0153x over previous
#include <cuda_runtime.h>
#include <math.h>
#include <stdint.h>

// Problem constants
#define BATCH   8192
#define DIM     256
#define NCOEF   5
#define KRED    1024          // reduced K: (NCOEF-1) coefficients per input dim
#define NLAYERS 2
#define LN_EPS  1e-6f

// ---------------------------------------------------------------------------
// Scratch (static device globals)
// ---------------------------------------------------------------------------
__device__ float g_dm[BATCH * KRED];             // design matrix [B][K], tf32-rounded
__device__ float g_h [BATCH * DIM];              // intermediate activations
__device__ float g_Bn[NLAYERS * DIM * KRED];     // B as [l][o][k], tf32-rounded
__device__ float g_bias[NLAYERS * DIM];          // sum_i coefs[l][i][o][0] (exact fp32)

// ---------------------------------------------------------------------------
// Helpers
// ---------------------------------------------------------------------------
__device__ __forceinline__ float to_tf32(float v) {
    uint32_t t;
    asm("cvt.rna.tf32.f32 %0, %1;" : "=r"(t) : "f"(v));
    return __uint_as_float(t);
}

__device__ __forceinline__ void mma_tf32_16n8k8(float* d, const uint32_t* a,
                                                const uint32_t* b) {
    asm volatile(
        "mma.sync.aligned.m16n8k8.row.col.f32.tf32.tf32.f32 "
        "{%0,%1,%2,%3}, {%4,%5,%6,%7}, {%8,%9}, {%0,%1,%2,%3};"
        : "+f"(d[0]), "+f"(d[1]), "+f"(d[2]), "+f"(d[3])
        : "r"(a[0]), "r"(a[1]), "r"(a[2]), "r"(a[3]),
          "r"(b[0]), "r"(b[1]));
}

// ---------------------------------------------------------------------------
// Kernel: build Bn[l][o][k], k = i*4 + (c-1), c in 1..4 ; tf32-rounded
// ---------------------------------------------------------------------------
__global__ void build_Bn(const float* __restrict__ coefs,
                         float* __restrict__ Bn) {
    int idx = blockIdx.x * blockDim.x + threadIdx.x;
    const int total = NLAYERS * DIM * KRED;
    if (idx >= total) return;
    int k = idx & (KRED - 1);
    int o = (idx >> 10) & (DIM - 1);
    int l = idx >> 18;
    int i = k >> 2;
    int c = (k & 3) + 1;
    Bn[idx] = to_tf32(coefs[(((size_t)(l * DIM + i)) * DIM + o) * NCOEF + c]);
}

// ---------------------------------------------------------------------------
// Kernel: bias[l][o] = sum_i coefs[l][i][o][0]  (exact fp32)
// ---------------------------------------------------------------------------
__global__ void __launch_bounds__(128)
build_bias(const float* __restrict__ coefs, float* __restrict__ bias) {
    int lo = blockIdx.x;            // 0..511
    int l = lo >> 8, o = lo & 255;
    float s = 0.0f;
    for (int i = threadIdx.x; i < DIM; i += 128)
        s += coefs[(((size_t)(l * DIM + i)) * DIM + o) * NCOEF];
    #pragma unroll
    for (int off = 16; off; off >>= 1) s += __shfl_xor_sync(0xFFFFFFFFu, s, off);
    __shared__ float red[4];
    if ((threadIdx.x & 31) == 0) red[threadIdx.x >> 5] = s;
    __syncthreads();
    if (threadIdx.x == 0)
        bias[lo] = red[0] + red[1] + red[2] + red[3];
}

// ---------------------------------------------------------------------------
// Kernel: LayerNorm + tanh + Jacobi (P1..P4), tf32-rounded float4 stores.
// ---------------------------------------------------------------------------
__global__ void __launch_bounds__(DIM)
ln_jacobi(const float* __restrict__ h,
          const float* __restrict__ scale,
          const float* __restrict__ bias,
          const float* __restrict__ alphas,
          int layer,
          float* __restrict__ dm) {
    const int b = blockIdx.x;
    const int i = threadIdx.x;

    float v = h[b * DIM + i];
    __shared__ float red[8];

    float s = v;
    #pragma unroll
    for (int off = 16; off; off >>= 1) s += __shfl_xor_sync(0xFFFFFFFFu, s, off);
    if ((i & 31) == 0) red[i >> 5] = s;
    __syncthreads();
    float mu = (red[0] + red[1] + red[2] + red[3] +
                red[4] + red[5] + red[6] + red[7]) * (1.0f / DIM);
    __syncthreads();

    float d = v - mu;
    float s2 = d * d;
    #pragma unroll
    for (int off = 16; off; off >>= 1) s2 += __shfl_xor_sync(0xFFFFFFFFu, s2, off);
    if ((i & 31) == 0) red[i >> 5] = s2;
    __syncthreads();
    float var = (red[0] + red[1] + red[2] + red[3] +
                 red[4] + red[5] + red[6] + red[7]) * (1.0f / DIM);

    float hn = d * rsqrtf(var + LN_EPS) * scale[i] + bias[i];
    float x  = tanhf(hn);
    float a  = tanhf(alphas[layer]);

    float P[NCOEF];
    P[0] = 1.0f;
    P[1] = (a + 1.0f) * x;
    #pragma unroll
    for (int k = 2; k < NCOEF; k++) {
        float kf = (float)k;
        float t  = 2.0f * kf + 2.0f * a;
        float A  = 2.0f * kf * (kf + 2.0f * a) * (t - 2.0f);
        float B  = (t - 1.0f) * t * (t - 2.0f);
        float C  = 2.0f * (kf + a - 1.0f) * (kf + a - 1.0f) * t;
        P[k] = (B * x * P[k - 1] - C * P[k - 2]) / A;
    }

    float4 out = make_float4(to_tf32(P[1]), to_tf32(P[2]),
                             to_tf32(P[3]), to_tf32(P[4]));
    *(float4*)(dm + (size_t)b * KRED + i * 4) = out;
}

// ---------------------------------------------------------------------------
// tf32 mma.sync GEMM: C[M,N] = (A[M,K] @ Bn^T + bias) / DIM
//   A = dm [8192,1024] row-major, Bn = [256,1024] (K-major rows = col-major B)
// CTA 128x128 tile, BK=32, double-buffered dynamic smem (pad 36), 256 thr.
// Warp layout 2 (m) x 4 (n): each warp 64 rows x 32 cols = 4x4 m16n8 tiles.
// ---------------------------------------------------------------------------
#define GK        KRED
#define NCHUNK    (GK / 32)       // 32
#define SPAD      36              // floats per smem row (32 + 4)
#define SM_TILE_F (128 * SPAD)    // 4608 floats per tile buffer
#define SMEM_GEMM_BYTES (4 * SM_TILE_F * 4)   // A0,A1,B0,B1 = 73728 B

__global__ void __launch_bounds__(256, 1)
gemm_mma(const float* __restrict__ A,
         const float* __restrict__ Bn,
         const float* __restrict__ bias,
         float* __restrict__ C) {
    extern __shared__ float sm[];
    float* sA[2] = { sm,                sm + SM_TILE_F     };
    float* sB[2] = { sm + 2*SM_TILE_F,  sm + 3*SM_TILE_F   };

    const int tid = threadIdx.x;
    const int lid = tid & 31;
    const int wid = tid >> 5;
    const int warp_m = wid & 1;       // 0..1 (64 rows each)
    const int warp_n = wid >> 1;      // 0..3 (32 cols each)
    const int qr = lid >> 2;          // 0..7
    const int qc = lid & 3;           // 0..3

    const int bm = blockIdx.x * 128;
    const int bn = blockIdx.y * 128;

    // global->reg load indices: f = tid + it*256; row = f/8, c4 = f%8
    const int gr = tid >> 3;          // 0..31  (+ it*32)
    const int gc = (tid & 7) * 4;     // 0,4,...,28

    float acc[4][4][4];
    #pragma unroll
    for (int mt = 0; mt < 4; mt++)
        #pragma unroll
        for (int nt = 0; nt < 4; nt++)
            #pragma unroll
            for (int j = 0; j < 4; j++) acc[mt][nt][j] = 0.0f;

    // preload chunk 0
    float4 pa[4], pb[4];
    #pragma unroll
    for (int it = 0; it < 4; it++) {
        int r = gr + it * 32;
        pa[it] = *(const float4*)(A  + (size_t)(bm + r) * GK + gc);
        pb[it] = *(const float4*)(Bn + (size_t)(bn + r) * GK + gc);
    }
    #pragma unroll
    for (int it = 0; it < 4; it++) {
        int r = gr + it * 32;
        *(float4*)(sA[0] + r * SPAD + gc) = pa[it];
        *(float4*)(sB[0] + r * SPAD + gc) = pb[it];
    }
    __syncthreads();

    #pragma unroll 1
    for (int c = 0; c < NCHUNK; c++) {
        const int buf = c & 1;

        if (c + 1 < NCHUNK) {
            const int kc = (c + 1) * 32;
            #pragma unroll
            for (int it = 0; it < 4; it++) {
                int r = gr + it * 32;
                pa[it] = *(const float4*)(A  + (size_t)(bm + r) * GK + kc + gc);
                pb[it] = *(const float4*)(Bn + (size_t)(bn + r) * GK + kc + gc);
            }
        }

        // compute on smem[buf]
        const float* Abase = sA[buf] + (warp_m * 64 + qr) * SPAD + qc;
        const float* Bbase = sB[buf] + (warp_n * 32 + qr) * SPAD + qc;
        #pragma unroll
        for (int ks = 0; ks < 4; ks++) {
            uint32_t af[4][4], bf[4][2];
            #pragma unroll
            for (int mt = 0; mt < 4; mt++) {
                const float* p = Abase + mt * 16 * SPAD + ks * 8;
                af[mt][0] = __float_as_uint(p[0]);
                af[mt][1] = __float_as_uint(p[8 * SPAD]);
                af[mt][2] = __float_as_uint(p[4]);
                af[mt][3] = __float_as_uint(p[8 * SPAD + 4]);
            }
            #pragma unroll
            for (int nt = 0; nt < 4; nt++) {
                const float* p = Bbase + nt * 8 * SPAD + ks * 8;
                bf[nt][0] = __float_as_uint(p[0]);
                bf[nt][1] = __float_as_uint(p[4]);
            }
            #pragma unroll
            for (int mt = 0; mt < 4; mt++)
                #pragma unroll
                for (int nt = 0; nt < 4; nt++)
                    mma_tf32_16n8k8(acc[mt][nt], af[mt], bf[nt]);
        }
        __syncthreads();

        if (c + 1 < NCHUNK) {
            #pragma unroll
            for (int it = 0; it < 4; it++) {
                int r = gr + it * 32;
                *(float4*)(sA[buf ^ 1] + r * SPAD + gc) = pa[it];
                *(float4*)(sB[buf ^ 1] + r * SPAD + gc) = pb[it];
            }
            __syncthreads();
        }
    }

    // epilogue: C = (acc + bias) * (1/DIM)
    const float inv = 1.0f / (float)DIM;
    const int r0 = bm + warp_m * 64 + qr;
    const int c0 = bn + warp_n * 32 + qc * 2;
    #pragma unroll
    for (int mt = 0; mt < 4; mt++) {
        #pragma unroll
        for (int nt = 0; nt < 4; nt++) {
            int col = c0 + nt * 8;
            float2 bv = *(const float2*)(bias + col);
            int row = r0 + mt * 16;
            float2 o0, o1;
            o0.x = (acc[mt][nt][0] + bv.x) * inv;
            o0.y = (acc[mt][nt][1] + bv.y) * inv;
            o1.x = (acc[mt][nt][2] + bv.x) * inv;
            o1.y = (acc[mt][nt][3] + bv.y) * inv;
            *(float2*)(C + (size_t)row * DIM + col)       = o0;
            *(float2*)(C + (size_t)(row + 8) * DIM + col) = o1;
        }
    }
}

// ---------------------------------------------------------------------------
// Launch
// ---------------------------------------------------------------------------
extern "C" void kernel_launch(void* const* d_in, const int* in_sizes, int n_in,
                              void* d_out, int out_size) {
    const float* x        = (const float*)d_in[0];
    const float* coefs    = (const float*)d_in[1];
    const float* alphas   = (const float*)d_in[2];
    const float* ln_scale = (const float*)d_in[3];
    const float* ln_bias  = (const float*)d_in[4];
    float* out = (float*)d_out;

    float* dm;   cudaGetSymbolAddress((void**)&dm,   g_dm);
    float* hbuf; cudaGetSymbolAddress((void**)&hbuf, g_h);
    float* Bn;   cudaGetSymbolAddress((void**)&Bn,   g_Bn);
    float* bias; cudaGetSymbolAddress((void**)&bias, g_bias);

    cudaFuncSetAttribute(gemm_mma, cudaFuncAttributeMaxDynamicSharedMemorySize,
                         SMEM_GEMM_BYTES);

    {
        int total = NLAYERS * DIM * KRED;
        build_Bn<<<(total + 255) / 256, 256>>>(coefs, Bn);
        build_bias<<<NLAYERS * DIM, 128>>>(coefs, bias);
    }

    dim3 ggrid(BATCH / 128, DIM / 128);

    // Layer 0
    ln_jacobi<<<BATCH, DIM>>>(x, ln_scale, ln_bias, alphas, 0, dm);
    gemm_mma<<<ggrid, 256, SMEM_GEMM_BYTES>>>(dm, Bn, bias, hbuf);

    // Layer 1
    ln_jacobi<<<BATCH, DIM>>>(hbuf, ln_scale + DIM, ln_bias + DIM, alphas, 1, dm);
    gemm_mma<<<ggrid, 256, SMEM_GEMM_BYTES>>>(dm, Bn + (size_t)DIM * KRED,
                                              bias + DIM, out);
}

// round 4
// speedup vs baseline: 3.8487x; 1.2764x over previous
#include <cuda_runtime.h>
#include <math.h>
#include <stdint.h>

// Problem constants
#define BATCH   8192
#define DIM     256
#define NCOEF   5
#define KRED    1024
#define NLAYERS 2
#define LN_EPS  1e-6f

// ---------------------------------------------------------------------------
// Scratch
// ---------------------------------------------------------------------------
__device__ float g_dm[BATCH * KRED];
__device__ float g_h [BATCH * DIM];
__device__ float g_Bn[NLAYERS * DIM * KRED];
__device__ float g_bias[NLAYERS * DIM];

// ---------------------------------------------------------------------------
// Helpers
// ---------------------------------------------------------------------------
__device__ __forceinline__ float to_tf32(float v) {
    uint32_t t;
    asm("cvt.rna.tf32.f32 %0, %1;" : "=r"(t) : "f"(v));
    return __uint_as_float(t);
}
__device__ __forceinline__ uint32_t smem_u32(const void* p) {
    uint32_t a;
    asm("{ .reg .u64 t; cvta.to.shared.u64 t, %1; cvt.u32.u64 %0, t; }"
        : "=r"(a) : "l"(p));
    return a;
}
__device__ __forceinline__ void mma_tf32_16n8k8(float* d, const uint32_t* a,
                                                const uint32_t* b) {
    asm volatile(
        "mma.sync.aligned.m16n8k8.row.col.f32.tf32.tf32.f32 "
        "{%0,%1,%2,%3}, {%4,%5,%6,%7}, {%8,%9}, {%0,%1,%2,%3};"
        : "+f"(d[0]), "+f"(d[1]), "+f"(d[2]), "+f"(d[3])
        : "r"(a[0]), "r"(a[1]), "r"(a[2]), "r"(a[3]),
          "r"(b[0]), "r"(b[1]));
}
#define LDSM4(r0, r1, r2, r3, addr) \
    asm volatile("ldmatrix.sync.aligned.m8n8.x4.shared.b16 {%0,%1,%2,%3}, [%4];" \
        : "=r"(r0), "=r"(r1), "=r"(r2), "=r"(r3) : "r"(addr))
#define CP_ASYNC16(dst, src) \
    asm volatile("cp.async.ca.shared.global [%0], [%1], 16;" \
        :: "r"(dst), "l"(src))
#define CP_COMMIT()  asm volatile("cp.async.commit_group;" ::: "memory")
#define CP_WAIT2()   asm volatile("cp.async.wait_group 2;"  ::: "memory")

// ---------------------------------------------------------------------------
// build Bn[l][o][k], k = i*4 + (c-1), tf32-rounded
// ---------------------------------------------------------------------------
__global__ void build_Bn(const float* __restrict__ coefs,
                         float* __restrict__ Bn) {
    int idx = blockIdx.x * blockDim.x + threadIdx.x;
    const int total = NLAYERS * DIM * KRED;
    if (idx >= total) return;
    int k = idx & (KRED - 1);
    int o = (idx >> 10) & (DIM - 1);
    int l = idx >> 18;
    int i = k >> 2;
    int c = (k & 3) + 1;
    Bn[idx] = to_tf32(coefs[(((size_t)(l * DIM + i)) * DIM + o) * NCOEF + c]);
}

// ---------------------------------------------------------------------------
// bias[l][o] = sum_i coefs[l][i][o][0]  (exact fp32)
// ---------------------------------------------------------------------------
__global__ void __launch_bounds__(128)
build_bias(const float* __restrict__ coefs, float* __restrict__ bias) {
    int lo = blockIdx.x;
    int l = lo >> 8, o = lo & 255;
    float s = 0.0f;
    for (int i = threadIdx.x; i < DIM; i += 128)
        s += coefs[(((size_t)(l * DIM + i)) * DIM + o) * NCOEF];
    #pragma unroll
    for (int off = 16; off; off >>= 1) s += __shfl_xor_sync(0xFFFFFFFFu, s, off);
    __shared__ float red[4];
    if ((threadIdx.x & 31) == 0) red[threadIdx.x >> 5] = s;
    __syncthreads();
    if (threadIdx.x == 0)
        bias[lo] = red[0] + red[1] + red[2] + red[3];
}

// ---------------------------------------------------------------------------
// LayerNorm + tanh + Jacobi (P1..P4), tf32-rounded float4 stores.
// ---------------------------------------------------------------------------
__global__ void __launch_bounds__(DIM)
ln_jacobi(const float* __restrict__ h,
          const float* __restrict__ scale,
          const float* __restrict__ bias,
          const float* __restrict__ alphas,
          int layer,
          float* __restrict__ dm) {
    const int b = blockIdx.x;
    const int i = threadIdx.x;

    float v = h[b * DIM + i];
    __shared__ float red[8];

    float s = v;
    #pragma unroll
    for (int off = 16; off; off >>= 1) s += __shfl_xor_sync(0xFFFFFFFFu, s, off);
    if ((i & 31) == 0) red[i >> 5] = s;
    __syncthreads();
    float mu = (red[0] + red[1] + red[2] + red[3] +
                red[4] + red[5] + red[6] + red[7]) * (1.0f / DIM);
    __syncthreads();

    float d = v - mu;
    float s2 = d * d;
    #pragma unroll
    for (int off = 16; off; off >>= 1) s2 += __shfl_xor_sync(0xFFFFFFFFu, s2, off);
    if ((i & 31) == 0) red[i >> 5] = s2;
    __syncthreads();
    float var = (red[0] + red[1] + red[2] + red[3] +
                 red[4] + red[5] + red[6] + red[7]) * (1.0f / DIM);

    float hn = d * rsqrtf(var + LN_EPS) * scale[i] + bias[i];
    float x  = tanhf(hn);
    float a  = tanhf(alphas[layer]);

    float P[NCOEF];
    P[0] = 1.0f;
    P[1] = (a + 1.0f) * x;
    #pragma unroll
    for (int k = 2; k < NCOEF; k++) {
        float kf = (float)k;
        float t  = 2.0f * kf + 2.0f * a;
        float A  = 2.0f * kf * (kf + 2.0f * a) * (t - 2.0f);
        float B  = (t - 1.0f) * t * (t - 2.0f);
        float C  = 2.0f * (kf + a - 1.0f) * (kf + a - 1.0f) * t;
        P[k] = (B * x * P[k - 1] - C * P[k - 2]) / A;
    }

    float4 out = make_float4(to_tf32(P[1]), to_tf32(P[2]),
                             to_tf32(P[3]), to_tf32(P[4]));
    *(float4*)(dm + (size_t)b * KRED + i * 4) = out;
}

// ---------------------------------------------------------------------------
// tf32 mma.sync GEMM, cp.async 4-stage pipeline + ldmatrix fragments.
// C[M,N] = (A[M,K] @ Bn^T + bias) / DIM
// CTA 128x128, BK=32, 512 threads (16 warps, 4x4 warp grid, 32x32 warp tile).
// ---------------------------------------------------------------------------
#define GK        KRED
#define NCHUNK    (GK / 32)           // 32
#define STAGES    4
#define SPAD      36                  // floats per smem row
#define TILE_F    (128 * SPAD)        // 4608 floats per operand tile
#define STAGE_B   (2 * TILE_F * 4)    // bytes per stage (A+B) = 36864
#define SMEM_GEMM_BYTES (STAGES * STAGE_B)   // 147456

__global__ void __launch_bounds__(512, 1)
gemm_mma(const float* __restrict__ A,
         const float* __restrict__ Bn,
         const float* __restrict__ bias,
         float* __restrict__ C) {
    extern __shared__ float sm[];
    const uint32_t sb = smem_u32(sm);

    const int tid = threadIdx.x;
    const int lid = tid & 31;
    const int wid = tid >> 5;
    const int warp_m = wid & 3;       // 0..3, 32 rows each
    const int warp_n = wid >> 2;      // 0..3, 32 cols each
    const int qr = lid >> 2;          // 0..7
    const int qc = lid & 3;           // 0..3

    const int bm = blockIdx.x * 128;
    const int bn = blockIdx.y * 128;

    // cp.async indices: f = tid + it*512 -> row f/8, float4 col f%8
    const int gr = tid >> 3;           // 0..63 (+64 for it=1)
    const int gc = (tid & 7) * 4;

    // ldmatrix per-lane base offsets (bytes)
    const int g = lid >> 3, lr = lid & 7;
    const uint32_t a_off =
        (uint32_t)(((warp_m * 32 + ((g & 1) << 3) + lr) * SPAD + (g >> 1) * 4) * 4);
    const uint32_t b_off =
        (uint32_t)(((warp_n * 32 + ((g >> 1) << 3) + lr) * SPAD + (g & 1) * 4) * 4);

    float acc[2][4][4];
    #pragma unroll
    for (int mt = 0; mt < 2; mt++)
        #pragma unroll
        for (int nt = 0; nt < 4; nt++)
            #pragma unroll
            for (int j = 0; j < 4; j++) acc[mt][nt][j] = 0.0f;

    // issue one stage of cp.async loads
    auto issue = [&](int stage, int kc) {
        const uint32_t st = sb + (uint32_t)stage * STAGE_B;
        #pragma unroll
        for (int it = 0; it < 2; it++) {
            int r = gr + it * 64;
            const float* ga = A  + (size_t)(bm + r) * GK + kc + gc;
            const float* gb = Bn + (size_t)(bn + r) * GK + kc + gc;
            uint32_t d = (uint32_t)((r * SPAD + gc) * 4);
            CP_ASYNC16(st + d, ga);
            CP_ASYNC16(st + TILE_F * 4 + d, gb);
        }
        CP_COMMIT();
    };

    // prologue: stages 0..2
    issue(0, 0);
    issue(1, 32);
    issue(2, 64);

    #pragma unroll 1
    for (int c = 0; c < NCHUNK; c++) {
        CP_WAIT2();
        __syncthreads();

        if (c + 3 < NCHUNK) issue((c + 3) & (STAGES - 1), (c + 3) * 32);
        else CP_COMMIT();   // keep group count constant for wait_group 2

        const uint32_t stA = sb + (uint32_t)(c & (STAGES - 1)) * STAGE_B;
        const uint32_t stB = stA + TILE_F * 4;

        #pragma unroll
        for (int ks = 0; ks < 4; ks++) {
            uint32_t af[2][4], bf[4][2];
            #pragma unroll
            for (int mt = 0; mt < 2; mt++)
                LDSM4(af[mt][0], af[mt][1], af[mt][2], af[mt][3],
                      stA + a_off + (uint32_t)((mt * 16 * SPAD + ks * 8) * 4));
            #pragma unroll
            for (int p = 0; p < 2; p++)
                LDSM4(bf[2 * p][0], bf[2 * p][1], bf[2 * p + 1][0], bf[2 * p + 1][1],
                      stB + b_off + (uint32_t)((p * 16 * SPAD + ks * 8) * 4));
            #pragma unroll
            for (int mt = 0; mt < 2; mt++)
                #pragma unroll
                for (int nt = 0; nt < 4; nt++)
                    mma_tf32_16n8k8(acc[mt][nt], af[mt], bf[nt]);
        }
    }

    // epilogue: C = (acc + bias) / DIM
    const float inv = 1.0f / (float)DIM;
    const int r0 = bm + warp_m * 32 + qr;
    const int c0 = bn + warp_n * 32 + qc * 2;
    #pragma unroll
    for (int mt = 0; mt < 2; mt++) {
        #pragma unroll
        for (int nt = 0; nt < 4; nt++) {
            int col = c0 + nt * 8;
            float2 bv = *(const float2*)(bias + col);
            int row = r0 + mt * 16;
            float2 o0, o1;
            o0.x = (acc[mt][nt][0] + bv.x) * inv;
            o0.y = (acc[mt][nt][1] + bv.y) * inv;
            o1.x = (acc[mt][nt][2] + bv.x) * inv;
            o1.y = (acc[mt][nt][3] + bv.y) * inv;
            *(float2*)(C + (size_t)row * DIM + col)       = o0;
            *(float2*)(C + (size_t)(row + 8) * DIM + col) = o1;
        }
    }
}

// ---------------------------------------------------------------------------
// Launch
// ---------------------------------------------------------------------------
extern "C" void kernel_launch(void* const* d_in, const int* in_sizes, int n_in,
                              void* d_out, int out_size) {
    const float* x        = (const float*)d_in[0];
    const float* coefs    = (const float*)d_in[1];
    const float* alphas   = (const float*)d_in[2];
    const float* ln_scale = (const float*)d_in[3];
    const float* ln_bias  = (const float*)d_in[4];
    float* out = (float*)d_out;

    float* dm;   cudaGetSymbolAddress((void**)&dm,   g_dm);
    float* hbuf; cudaGetSymbolAddress((void**)&hbuf, g_h);
    float* Bn;   cudaGetSymbolAddress((void**)&Bn,   g_Bn);
    float* bias; cudaGetSymbolAddress((void**)&bias, g_bias);

    cudaFuncSetAttribute(gemm_mma, cudaFuncAttributeMaxDynamicSharedMemorySize,
                         SMEM_GEMM_BYTES);

    {
        int total = NLAYERS * DIM * KRED;
        build_Bn<<<(total + 255) / 256, 256>>>(coefs, Bn);
        build_bias<<<NLAYERS * DIM, 128>>>(coefs, bias);
    }

    dim3 ggrid(BATCH / 128, DIM / 128);

    // Layer 0
    ln_jacobi<<<BATCH, DIM>>>(x, ln_scale, ln_bias, alphas, 0, dm);
    gemm_mma<<<ggrid, 512, SMEM_GEMM_BYTES>>>(dm, Bn, bias, hbuf);

    // Layer 1
    ln_jacobi<<<BATCH, DIM>>>(hbuf, ln_scale + DIM, ln_bias + DIM, alphas, 1, dm);
    gemm_mma<<<ggrid, 512, SMEM_GEMM_BYTES>>>(dm, Bn + (size_t)DIM * KRED,
                                              bias + DIM, out);
}

// round 5
// speedup vs baseline: 5.5947x; 1.4537x over previous
#include <cuda_runtime.h>
#include <cuda_fp16.h>
#include <math.h>
#include <stdint.h>

// Problem constants
#define BATCH   8192
#define DIM     256
#define KRED    1024
#define NCOEF   5
#define NLAYERS 2
#define LN_EPS  1e-6f

// ---------------------------------------------------------------------------
// Scratch
// ---------------------------------------------------------------------------
__device__ __half g_dm[BATCH * KRED];            // design matrix, fp16
__device__ float  g_h [BATCH * DIM];             // intermediate activations
__device__ __half g_Bn[NLAYERS * DIM * KRED];    // B as [l][o][k], fp16
__device__ float  g_bias[NLAYERS * DIM];         // exact fp32 P0 fold

// ---------------------------------------------------------------------------
// Helpers
// ---------------------------------------------------------------------------
__device__ __forceinline__ uint32_t smem_u32(const void* p) {
    uint32_t a;
    asm("{ .reg .u64 t; cvta.to.shared.u64 t, %1; cvt.u32.u64 %0, t; }"
        : "=r"(a) : "l"(p));
    return a;
}
__device__ __forceinline__ void mma_f16_16n8k16(float* d, const uint32_t* a,
                                                const uint32_t* b) {
    asm volatile(
        "mma.sync.aligned.m16n8k16.row.col.f32.f16.f16.f32 "
        "{%0,%1,%2,%3}, {%4,%5,%6,%7}, {%8,%9}, {%0,%1,%2,%3};"
        : "+f"(d[0]), "+f"(d[1]), "+f"(d[2]), "+f"(d[3])
        : "r"(a[0]), "r"(a[1]), "r"(a[2]), "r"(a[3]),
          "r"(b[0]), "r"(b[1]));
}
#define LDSM4(r0, r1, r2, r3, addr) \
    asm volatile("ldmatrix.sync.aligned.m8n8.x4.shared.b16 {%0,%1,%2,%3}, [%4];" \
        : "=r"(r0), "=r"(r1), "=r"(r2), "=r"(r3) : "r"(addr))
#define CP_ASYNC16(dst, src) \
    asm volatile("cp.async.ca.shared.global [%0], [%1], 16;" \
        :: "r"(dst), "l"(src))
#define CP_COMMIT()  asm volatile("cp.async.commit_group;" ::: "memory")
#define CP_WAIT2()   asm volatile("cp.async.wait_group 2;"  ::: "memory")

// ---------------------------------------------------------------------------
// build Bn[l][o][k], k = i*4 + (c-1), fp16-rounded
// ---------------------------------------------------------------------------
__global__ void build_Bn(const float* __restrict__ coefs,
                         __half* __restrict__ Bn) {
    int idx = blockIdx.x * blockDim.x + threadIdx.x;
    const int total = NLAYERS * DIM * KRED;
    if (idx >= total) return;
    int k = idx & (KRED - 1);
    int o = (idx >> 10) & (DIM - 1);
    int l = idx >> 18;
    int i = k >> 2;
    int c = (k & 3) + 1;
    Bn[idx] = __float2half_rn(
        coefs[(((size_t)(l * DIM + i)) * DIM + o) * NCOEF + c]);
}

// ---------------------------------------------------------------------------
// bias[l][o] = sum_i coefs[l][i][o][0]  (exact fp32)
// ---------------------------------------------------------------------------
__global__ void __launch_bounds__(128)
build_bias(const float* __restrict__ coefs, float* __restrict__ bias) {
    int lo = blockIdx.x;
    int l = lo >> 8, o = lo & 255;
    float s = 0.0f;
    for (int i = threadIdx.x; i < DIM; i += 128)
        s += coefs[(((size_t)(l * DIM + i)) * DIM + o) * NCOEF];
    #pragma unroll
    for (int off = 16; off; off >>= 1) s += __shfl_xor_sync(0xFFFFFFFFu, s, off);
    __shared__ float red[4];
    if ((threadIdx.x & 31) == 0) red[threadIdx.x >> 5] = s;
    __syncthreads();
    if (threadIdx.x == 0)
        bias[lo] = red[0] + red[1] + red[2] + red[3];
}

// ---------------------------------------------------------------------------
// LayerNorm + tanh + Jacobi (P1..P4), fp16 8-byte stores.
// ---------------------------------------------------------------------------
__global__ void __launch_bounds__(DIM)
ln_jacobi(const float* __restrict__ h,
          const float* __restrict__ scale,
          const float* __restrict__ bias,
          const float* __restrict__ alphas,
          int layer,
          __half* __restrict__ dm) {
    const int b = blockIdx.x;
    const int i = threadIdx.x;

    float v = h[b * DIM + i];
    __shared__ float red[8];

    float s = v;
    #pragma unroll
    for (int off = 16; off; off >>= 1) s += __shfl_xor_sync(0xFFFFFFFFu, s, off);
    if ((i & 31) == 0) red[i >> 5] = s;
    __syncthreads();
    float mu = (red[0] + red[1] + red[2] + red[3] +
                red[4] + red[5] + red[6] + red[7]) * (1.0f / DIM);
    __syncthreads();

    float d = v - mu;
    float s2 = d * d;
    #pragma unroll
    for (int off = 16; off; off >>= 1) s2 += __shfl_xor_sync(0xFFFFFFFFu, s2, off);
    if ((i & 31) == 0) red[i >> 5] = s2;
    __syncthreads();
    float var = (red[0] + red[1] + red[2] + red[3] +
                 red[4] + red[5] + red[6] + red[7]) * (1.0f / DIM);

    float hn = d * rsqrtf(var + LN_EPS) * scale[i] + bias[i];
    float x  = tanhf(hn);
    float a  = tanhf(alphas[layer]);

    float P[NCOEF];
    P[0] = 1.0f;
    P[1] = (a + 1.0f) * x;
    #pragma unroll
    for (int k = 2; k < NCOEF; k++) {
        float kf = (float)k;
        float t  = 2.0f * kf + 2.0f * a;
        float A  = 2.0f * kf * (kf + 2.0f * a) * (t - 2.0f);
        float B  = (t - 1.0f) * t * (t - 2.0f);
        float C  = 2.0f * (kf + a - 1.0f) * (kf + a - 1.0f) * t;
        P[k] = (B * x * P[k - 1] - C * P[k - 2]) / A;
    }

    __half2 o0 = __floats2half2_rn(P[1], P[2]);
    __half2 o1 = __floats2half2_rn(P[3], P[4]);
    uint2 pkt = make_uint2(*(uint32_t*)&o0, *(uint32_t*)&o1);
    *(uint2*)(dm + (size_t)b * KRED + i * 4) = pkt;
}

// ---------------------------------------------------------------------------
// fp16 mma.sync GEMM (fp32 accum): C = (A @ Bn^T + bias) / DIM
// A = dm [8192,1024] halves, Bn = [256,1024] halves (K-major rows).
// CTA 128x128, BK=64, 512 threads (16 warps, 4x4 grid, 32x32 warp tile).
// 4-stage cp.async pipeline, ldmatrix fragments.
// ---------------------------------------------------------------------------
#define GK        KRED
#define BK        64
#define NCHUNK    (GK / BK)           // 16
#define STAGES    4
#define ROWB      144                 // bytes per smem row (128 + 16 pad)
#define TILE_B    (128 * ROWB)        // 18432 bytes per operand tile
#define STAGE_B   (2 * TILE_B)        // 36864
#define SMEM_GEMM_BYTES (STAGES * STAGE_B)   // 147456

__global__ void __launch_bounds__(512, 1)
gemm_mma(const __half* __restrict__ A,
         const __half* __restrict__ Bn,
         const float* __restrict__ bias,
         float* __restrict__ C) {
    extern __shared__ char sm[];
    const uint32_t sb = smem_u32(sm);

    const int tid = threadIdx.x;
    const int lid = tid & 31;
    const int wid = tid >> 5;
    const int warp_m = wid & 3;       // 32 rows each
    const int warp_n = wid >> 2;      // 32 cols each
    const int qr = lid >> 2;
    const int qc = lid & 3;

    const int bm = blockIdx.x * 128;
    const int bn = blockIdx.y * 128;

    // cp.async: thread -> (row = tid/8 + it*64, 16B chunk = tid%8)
    const int gr = tid >> 3;
    const int gch = tid & 7;

    // ldmatrix lane offsets (bytes within a tile)
    const uint32_t a_loff =
        (uint32_t)((warp_m * 32 + (lid & 15)) * ROWB + ((lid >> 4) << 4));
    const uint32_t b_loff =
        (uint32_t)((warp_n * 32 + ((lid & 7) | ((lid >> 4) << 3))) * ROWB +
                   (((lid >> 3) & 1) << 4));

    float acc[2][4][4];
    #pragma unroll
    for (int mt = 0; mt < 2; mt++)
        #pragma unroll
        for (int nt = 0; nt < 4; nt++)
            #pragma unroll
            for (int j = 0; j < 4; j++) acc[mt][nt][j] = 0.0f;

    auto issue = [&](int stage, int kc) {   // kc in halves
        const uint32_t st = sb + (uint32_t)stage * STAGE_B;
        #pragma unroll
        for (int it = 0; it < 2; it++) {
            int r = gr + it * 64;
            const __half* ga = A  + (size_t)(bm + r) * GK + kc + gch * 8;
            const __half* gb = Bn + (size_t)(bn + r) * GK + kc + gch * 8;
            uint32_t d = (uint32_t)(r * ROWB + gch * 16);
            CP_ASYNC16(st + d, ga);
            CP_ASYNC16(st + TILE_B + d, gb);
        }
        CP_COMMIT();
    };

    issue(0, 0);
    issue(1, BK);
    issue(2, 2 * BK);

    #pragma unroll 1
    for (int c = 0; c < NCHUNK; c++) {
        CP_WAIT2();
        __syncthreads();

        if (c + 3 < NCHUNK) issue((c + 3) & (STAGES - 1), (c + 3) * BK);
        else CP_COMMIT();

        const uint32_t stA = sb + (uint32_t)(c & (STAGES - 1)) * STAGE_B;
        const uint32_t stB = stA + TILE_B;

        #pragma unroll
        for (int ks = 0; ks < 4; ks++) {          // 4 x k16 per BK=64
            uint32_t af[2][4], bf[4][2];
            #pragma unroll
            for (int mt = 0; mt < 2; mt++)
                LDSM4(af[mt][0], af[mt][1], af[mt][2], af[mt][3],
                      stA + a_loff + (uint32_t)(mt * 16 * ROWB + ks * 32));
            #pragma unroll
            for (int p = 0; p < 2; p++)
                LDSM4(bf[2 * p][0], bf[2 * p][1], bf[2 * p + 1][0], bf[2 * p + 1][1],
                      stB + b_loff + (uint32_t)(p * 16 * ROWB + ks * 32));
            #pragma unroll
            for (int mt = 0; mt < 2; mt++)
                #pragma unroll
                for (int nt = 0; nt < 4; nt++)
                    mma_f16_16n8k16(acc[mt][nt], af[mt], bf[nt]);
        }
    }

    // epilogue: C = (acc + bias) / DIM
    const float inv = 1.0f / (float)DIM;
    const int r0 = bm + warp_m * 32 + qr;
    const int c0 = bn + warp_n * 32 + qc * 2;
    #pragma unroll
    for (int mt = 0; mt < 2; mt++) {
        #pragma unroll
        for (int nt = 0; nt < 4; nt++) {
            int col = c0 + nt * 8;
            float2 bv = *(const float2*)(bias + col);
            int row = r0 + mt * 16;
            float2 o0, o1;
            o0.x = (acc[mt][nt][0] + bv.x) * inv;
            o0.y = (acc[mt][nt][1] + bv.y) * inv;
            o1.x = (acc[mt][nt][2] + bv.x) * inv;
            o1.y = (acc[mt][nt][3] + bv.y) * inv;
            *(float2*)(C + (size_t)row * DIM + col)       = o0;
            *(float2*)(C + (size_t)(row + 8) * DIM + col) = o1;
        }
    }
}

// ---------------------------------------------------------------------------
// Launch
// ---------------------------------------------------------------------------
extern "C" void kernel_launch(void* const* d_in, const int* in_sizes, int n_in,
                              void* d_out, int out_size) {
    const float* x        = (const float*)d_in[0];
    const float* coefs    = (const float*)d_in[1];
    const float* alphas   = (const float*)d_in[2];
    const float* ln_scale = (const float*)d_in[3];
    const float* ln_bias  = (const float*)d_in[4];
    float* out = (float*)d_out;

    __half* dm;  cudaGetSymbolAddress((void**)&dm,   g_dm);
    float* hbuf; cudaGetSymbolAddress((void**)&hbuf, g_h);
    __half* Bn;  cudaGetSymbolAddress((void**)&Bn,   g_Bn);
    float* bias; cudaGetSymbolAddress((void**)&bias, g_bias);

    cudaFuncSetAttribute(gemm_mma, cudaFuncAttributeMaxDynamicSharedMemorySize,
                         SMEM_GEMM_BYTES);

    {
        int total = NLAYERS * DIM * KRED;
        build_Bn<<<(total + 255) / 256, 256>>>(coefs, Bn);
        build_bias<<<NLAYERS * DIM, 128>>>(coefs, bias);
    }

    dim3 ggrid(BATCH / 128, DIM / 128);

    // Layer 0
    ln_jacobi<<<BATCH, DIM>>>(x, ln_scale, ln_bias, alphas, 0, dm);
    gemm_mma<<<ggrid, 512, SMEM_GEMM_BYTES>>>(dm, Bn, bias, hbuf);

    // Layer 1
    ln_jacobi<<<BATCH, DIM>>>(hbuf, ln_scale + DIM, ln_bias + DIM, alphas, 1, dm);
    gemm_mma<<<ggrid, 512, SMEM_GEMM_BYTES>>>(dm, Bn + (size_t)DIM * KRED,
                                              bias + DIM, out);
}

// round 6
// speedup vs baseline: 5.9735x; 1.0677x over previous
#include <cuda_runtime.h>
#include <cuda_fp16.h>
#include <math.h>
#include <stdint.h>

#define BATCH   8192
#define DIM     256
#define KRED    1024
#define NCOEF   5
#define NLAYERS 2
#define LN_EPS  1e-6f

// ---------------------------------------------------------------------------
// Scratch
// ---------------------------------------------------------------------------
__device__ float  g_h [BATCH * DIM];             // layer-0 output
__device__ __half g_Bn[NLAYERS * DIM * KRED];    // B as [l][o][k], fp16
__device__ float  g_bias[NLAYERS * DIM];         // exact fp32 P0 fold

// ---------------------------------------------------------------------------
// Helpers
// ---------------------------------------------------------------------------
__device__ __forceinline__ uint32_t smem_u32(const void* p) {
    uint32_t a;
    asm("{ .reg .u64 t; cvta.to.shared.u64 t, %1; cvt.u32.u64 %0, t; }"
        : "=r"(a) : "l"(p));
    return a;
}
__device__ __forceinline__ void mma_f16_16n8k16(float* d, const uint32_t* a,
                                                const uint32_t* b) {
    asm volatile(
        "mma.sync.aligned.m16n8k16.row.col.f32.f16.f16.f32 "
        "{%0,%1,%2,%3}, {%4,%5,%6,%7}, {%8,%9}, {%0,%1,%2,%3};"
        : "+f"(d[0]), "+f"(d[1]), "+f"(d[2]), "+f"(d[3])
        : "r"(a[0]), "r"(a[1]), "r"(a[2]), "r"(a[3]),
          "r"(b[0]), "r"(b[1]));
}
#define LDSM4(r0, r1, r2, r3, addr) \
    asm volatile("ldmatrix.sync.aligned.m8n8.x4.shared.b16 {%0,%1,%2,%3}, [%4];" \
        : "=r"(r0), "=r"(r1), "=r"(r2), "=r"(r3) : "r"(addr))
#define CP_ASYNC16(dst, src) \
    asm volatile("cp.async.ca.shared.global [%0], [%1], 16;" \
        :: "r"(dst), "l"(src))
#define CP_COMMIT()  asm volatile("cp.async.commit_group;" ::: "memory")
#define CP_WAIT1()   asm volatile("cp.async.wait_group 1;"  ::: "memory")
#define CP_WAIT2()   asm volatile("cp.async.wait_group 2;"  ::: "memory")

// ---------------------------------------------------------------------------
// build Bn[l][o][k], k = i*4 + (c-1), fp16
// ---------------------------------------------------------------------------
__global__ void build_Bn(const float* __restrict__ coefs,
                         __half* __restrict__ Bn) {
    int idx = blockIdx.x * blockDim.x + threadIdx.x;
    const int total = NLAYERS * DIM * KRED;
    if (idx >= total) return;
    int k = idx & (KRED - 1);
    int o = (idx >> 10) & (DIM - 1);
    int l = idx >> 18;
    int i = k >> 2;
    int c = (k & 3) + 1;
    Bn[idx] = __float2half_rn(
        coefs[(((size_t)(l * DIM + i)) * DIM + o) * NCOEF + c]);
}

// ---------------------------------------------------------------------------
// bias[l][o] = sum_i coefs[l][i][o][0]  (exact fp32)
// ---------------------------------------------------------------------------
__global__ void __launch_bounds__(128)
build_bias(const float* __restrict__ coefs, float* __restrict__ bias) {
    int lo = blockIdx.x;
    int l = lo >> 8, o = lo & 255;
    float s = 0.0f;
    for (int i = threadIdx.x; i < DIM; i += 128)
        s += coefs[(((size_t)(l * DIM + i)) * DIM + o) * NCOEF];
    #pragma unroll
    for (int off = 16; off; off >>= 1) s += __shfl_xor_sync(0xFFFFFFFFu, s, off);
    __shared__ float red[4];
    if ((threadIdx.x & 31) == 0) red[threadIdx.x >> 5] = s;
    __syncthreads();
    if (threadIdx.x == 0)
        bias[lo] = red[0] + red[1] + red[2] + red[3];
}

// ---------------------------------------------------------------------------
// Fused layer kernel: LN + tanh + Jacobi A-tile generation + fp16 HMMA GEMM.
// C[M,N] = ( jacobi(LN(h)) @ Bn^T + bias ) / DIM
// CTA 128x128, BK=64 (16 input dims/chunk), 512 threads (16 warps, 4x4 grid).
// B + h-slice through 4-stage cp.async; A generated in-kernel (2 buffers).
// ---------------------------------------------------------------------------
#define BK        64
#define NCHUNK    (KRED / BK)         // 16
#define ROWB      144                 // A/B smem row bytes (128 + 16 pad)
#define TILE_B    (128 * ROWB)        // 18432
#define HROWB     80                  // h-slice row bytes (64 + 16 pad)
#define HTILE     (128 * HROWB)       // 10240
#define SM_STATS  0                   // 128 rows x (mu, rsig) = 1024 B
#define SM_A      1024                // 2 x 18432 = 36864
#define SM_B      37888               // 4 x 18432 = 73728
#define SM_H      111616              // 4 x 10240 = 40960
#define SMEM_FUSED_BYTES 152576

__global__ void __launch_bounds__(512, 1)
fused_layer(const float* __restrict__ h,
            const __half* __restrict__ Bn,
            const float* __restrict__ biasP0,
            const float* __restrict__ lnscale,
            const float* __restrict__ lnbias,
            const float* __restrict__ alphas,
            int layer,
            float* __restrict__ C) {
    extern __shared__ char sm[];
    const uint32_t sb = smem_u32(sm);
    float* stats = (float*)sm;

    const int tid = threadIdx.x;
    const int lid = tid & 31;
    const int wid = tid >> 5;
    const int warp_m = wid & 3;
    const int warp_n = wid >> 2;
    const int qr = lid >> 2;
    const int qc = lid & 3;

    const int bm = blockIdx.x * 128;
    const int bn = blockIdx.y * 128;

    // Jacobi scalar coefficients (per-thread, tiny)
    const float a  = tanhf(alphas[layer]);
    float bb[3], cc[3];
    #pragma unroll
    for (int k = 2; k <= 4; k++) {
        float kf = (float)k;
        float t  = 2.0f * kf + 2.0f * a;
        float A  = 2.0f * kf * (kf + 2.0f * a) * (t - 2.0f);
        float B  = (t - 1.0f) * t * (t - 2.0f);
        float Cc = 2.0f * (kf + a - 1.0f) * (kf + a - 1.0f) * t;
        float invA = 1.0f / A;
        bb[k - 2] = B * invA;
        cc[k - 2] = Cc * invA;
    }
    const float p1c = a + 1.0f;

    // cp.async stage fill: B tile (2x16B/thread) + h slice (1x16B/thread)
    auto issue = [&](int stage, int ch) {
        const uint32_t stB = sb + SM_B + (uint32_t)stage * TILE_B;
        const uint32_t stH = sb + SM_H + (uint32_t)stage * HTILE;
        #pragma unroll
        for (int it = 0; it < 2; it++) {
            int idx = tid + it * 512;
            int row = idx >> 3, q8 = idx & 7;
            const __half* gb = Bn + (size_t)(bn + row) * KRED + ch * BK + q8 * 8;
            CP_ASYNC16(stB + row * ROWB + q8 * 16, gb);
        }
        {
            int row = tid >> 2, q4 = tid & 3;
            const float* gh = h + (size_t)(bm + row) * DIM + ch * 16 + q4 * 4;
            CP_ASYNC16(stH + row * HROWB + q4 * 16, gh);
        }
        CP_COMMIT();
    };

    // A-tile generation for chunk ch into buffer abuf
    auto genA = [&](int ch, int abuf) {
        const int i_loc = tid & 15;
        const int rbase = tid >> 4;          // 0..31
        const int col = ch * 16 + i_loc;
        const float sc = __ldg(lnscale + col);
        const float bi = __ldg(lnbias + col);
        const char* hbase = sm + SM_H + (ch & 3) * HTILE;
        char* abase = sm + SM_A + abuf * TILE_B;
        #pragma unroll
        for (int p = 0; p < 4; p++) {
            int row = rbase + p * 32;
            float v  = *(const float*)(hbase + row * HROWB + i_loc * 4);
            float mu = stats[2 * row];
            float rs = stats[2 * row + 1];
            float x  = tanhf((v - mu) * rs * sc + bi);
            float P1 = p1c * x;
            float P2 = bb[0] * x * P1 - cc[0];
            float P3 = bb[1] * x * P2 - cc[1] * P1;
            float P4 = bb[2] * x * P3 - cc[2] * P2;
            __half2 h0 = __floats2half2_rn(P1, P2);
            __half2 h1 = __floats2half2_rn(P3, P4);
            *(uint2*)(abase + row * ROWB + i_loc * 8) =
                make_uint2(*(uint32_t*)&h0, *(uint32_t*)&h1);
        }
    };

    // prologue: start pipeline, compute row stats
    issue(0, 0);
    issue(1, 1);
    issue(2, 2);

    {   // LN stats: warp w handles rows w*8..w*8+7
        #pragma unroll 1
        for (int j = 0; j < 8; j++) {
            int row = wid * 8 + j;
            const float4* p = (const float4*)(h + (size_t)(bm + row) * DIM) + lid * 2;
            float4 u = p[0], v = p[1];
            float s  = u.x + u.y + u.z + u.w + v.x + v.y + v.z + v.w;
            float s2 = u.x*u.x + u.y*u.y + u.z*u.z + u.w*u.w
                     + v.x*v.x + v.y*v.y + v.z*v.z + v.w*v.w;
            #pragma unroll
            for (int off = 16; off; off >>= 1) {
                s  += __shfl_xor_sync(0xFFFFFFFFu, s,  off);
                s2 += __shfl_xor_sync(0xFFFFFFFFu, s2, off);
            }
            if (lid == 0) {
                float mu  = s * (1.0f / DIM);
                float var = s2 * (1.0f / DIM) - mu * mu;
                stats[2 * row]     = mu;
                stats[2 * row + 1] = rsqrtf(var + LN_EPS);
            }
        }
    }

    CP_WAIT2();          // stage 0 arrived
    __syncthreads();     // stats + h-slice 0 visible
    genA(0, 0);

    // ldmatrix lane offsets
    const uint32_t a_loff =
        (uint32_t)((warp_m * 32 + (lid & 15)) * ROWB + ((lid >> 4) << 4));
    const uint32_t b_loff =
        (uint32_t)((warp_n * 32 + ((lid & 7) | ((lid >> 4) << 3))) * ROWB +
                   (((lid >> 3) & 1) << 4));

    float acc[2][4][4];
    #pragma unroll
    for (int mt = 0; mt < 2; mt++)
        #pragma unroll
        for (int nt = 0; nt < 4; nt++)
            #pragma unroll
            for (int j = 0; j < 4; j++) acc[mt][nt][j] = 0.0f;

    #pragma unroll 1
    for (int c = 0; c < NCHUNK; c++) {
        CP_WAIT1();          // stages up to c+1 arrived
        __syncthreads();     // A[c] STS + stage data visible to all

        if (c + 3 < NCHUNK) issue((c + 3) & 3, c + 3);
        else CP_COMMIT();

        const uint32_t stA = sb + SM_A + (uint32_t)(c & 1) * TILE_B;
        const uint32_t stB = sb + SM_B + (uint32_t)(c & 3) * TILE_B;

        #pragma unroll
        for (int ks = 0; ks < 4; ks++) {
            uint32_t af[2][4], bf[4][2];
            #pragma unroll
            for (int mt = 0; mt < 2; mt++)
                LDSM4(af[mt][0], af[mt][1], af[mt][2], af[mt][3],
                      stA + a_loff + (uint32_t)(mt * 16 * ROWB + ks * 32));
            #pragma unroll
            for (int p = 0; p < 2; p++)
                LDSM4(bf[2*p][0], bf[2*p][1], bf[2*p+1][0], bf[2*p+1][1],
                      stB + b_loff + (uint32_t)(p * 16 * ROWB + ks * 32));
            #pragma unroll
            for (int mt = 0; mt < 2; mt++)
                #pragma unroll
                for (int nt = 0; nt < 4; nt++)
                    mma_f16_16n8k16(acc[mt][nt], af[mt], bf[nt]);
        }

        if (c + 1 < NCHUNK) genA(c + 1, (c + 1) & 1);
    }

    // epilogue: C = (acc + bias) / DIM
    const float inv = 1.0f / (float)DIM;
    const int r0 = bm + warp_m * 32 + qr;
    const int c0 = bn + warp_n * 32 + qc * 2;
    #pragma unroll
    for (int mt = 0; mt < 2; mt++) {
        #pragma unroll
        for (int nt = 0; nt < 4; nt++) {
            int col = c0 + nt * 8;
            float2 bv = *(const float2*)(biasP0 + col);
            int row = r0 + mt * 16;
            float2 o0, o1;
            o0.x = (acc[mt][nt][0] + bv.x) * inv;
            o0.y = (acc[mt][nt][1] + bv.y) * inv;
            o1.x = (acc[mt][nt][2] + bv.x) * inv;
            o1.y = (acc[mt][nt][3] + bv.y) * inv;
            *(float2*)(C + (size_t)row * DIM + col)       = o0;
            *(float2*)(C + (size_t)(row + 8) * DIM + col) = o1;
        }
    }
}

// ---------------------------------------------------------------------------
// Launch
// ---------------------------------------------------------------------------
extern "C" void kernel_launch(void* const* d_in, const int* in_sizes, int n_in,
                              void* d_out, int out_size) {
    const float* x        = (const float*)d_in[0];
    const float* coefs    = (const float*)d_in[1];
    const float* alphas   = (const float*)d_in[2];
    const float* ln_scale = (const float*)d_in[3];
    const float* ln_bias  = (const float*)d_in[4];
    float* out = (float*)d_out;

    float* hbuf; cudaGetSymbolAddress((void**)&hbuf, g_h);
    __half* Bn;  cudaGetSymbolAddress((void**)&Bn,   g_Bn);
    float* bias; cudaGetSymbolAddress((void**)&bias, g_bias);

    cudaFuncSetAttribute(fused_layer,
                         cudaFuncAttributeMaxDynamicSharedMemorySize,
                         SMEM_FUSED_BYTES);

    {
        int total = NLAYERS * DIM * KRED;
        build_Bn<<<(total + 255) / 256, 256>>>(coefs, Bn);
        build_bias<<<NLAYERS * DIM, 128>>>(coefs, bias);
    }

    dim3 ggrid(BATCH / 128, DIM / 128);

    fused_layer<<<ggrid, 512, SMEM_FUSED_BYTES>>>(
        x, Bn, bias, ln_scale, ln_bias, alphas, 0, hbuf);

    fused_layer<<<ggrid, 512, SMEM_FUSED_BYTES>>>(
        hbuf, Bn + (size_t)DIM * KRED, bias + DIM,
        ln_scale + DIM, ln_bias + DIM, alphas, 1, out);
}